// round 15
// baseline (speedup 1.0000x reference)
#include <cuda_runtime.h>

// Problem constants (fixed shapes from setup_inputs)
#define BB        4
#define NIMG      16      // b*n
#define CC        256
#define HWC       4096    // 64*64
#define KD        128
#define OCH       256
#define IC2       512
#define ICEFF     384     // 256 query channels + 128 folded k-channels
#define EPSF      1e-6f
#define STAGE_NUM 5

typedef unsigned long long ull;

// ---------------------------------------------------------------------------
// f32x2 packed-FMA helpers (sm_100+): 2 fp32 FMAs per instruction, bit-exact.
// ---------------------------------------------------------------------------
__device__ __forceinline__ ull f32x2_pack(float x, float y) {
    ull r;
    asm("mov.b64 %0, {%1, %2};" : "=l"(r)
        : "r"(__float_as_uint(x)), "r"(__float_as_uint(y)));
    return r;
}
__device__ __forceinline__ void f32x2_fma(ull& d, ull a, ull b) {
    asm("fma.rn.f32x2 %0, %1, %2, %0;" : "+l"(d) : "l"(a), "l"(b));
}
__device__ __forceinline__ void f32x2_unpack(ull v, float& x, float& y) {
    unsigned lo, hi;
    asm("mov.b64 {%0, %1}, %2;" : "=r"(lo), "=r"(hi) : "l"(v));
    x = __uint_as_float(lo);
    y = __uint_as_float(hi);
}

// ---------------------------------------------------------------------------
// Device scratch (no cudaMalloc allowed)
// ---------------------------------------------------------------------------
__device__ float g_mu[BB * CC * KD];              // current mu   [b][c][k]
__device__ float g_mu_acc[BB * CC * KD];          // accumulation [b][c][k]
__device__ float g_colsum[BB * KD];               // softmax col sums [b][k]
__device__ float g_z[(size_t)BB * HWC * KD];      // EM z  [b][l][k]   (8 MB)
__device__ float g_qzt[(size_t)NIMG * KD * HWC];  // q_z^T [img][k][hw] (32 MB)
__device__ float g_wfold[(size_t)BB * OCH * KD * 9]; // folded w' [b][oc][k][tap]

// ---------------------------------------------------------------------------
// init mu: broadcast mu0 [1,C,K] to [B,C,K]
// ---------------------------------------------------------------------------
__global__ void k_init_mu(const float* __restrict__ mu0) {
    int i = blockIdx.x * blockDim.x + threadIdx.x;
    if (i < BB * CC * KD) g_mu[i] = mu0[i % (CC * KD)];
}

__global__ void k_zero_acc() {
    int i = blockIdx.x * blockDim.x + threadIdx.x;
    if (i < BB * CC * KD) g_mu_acc[i] = 0.f;
    if (i < BB * KD)      g_colsum[i] = 0.f;
}

// ---------------------------------------------------------------------------
// EM phase: z[b][l][k] = softmax_k( sum_c x[b][c][l] * mu[b][c][k] )
// Fused softmax + colsum accumulation in the epilogue (k-tile = full 128).
// Tile 128(l) x 128(k) x 16(c). 256 threads, 8x8/thread. grid (32, B)
// ---------------------------------------------------------------------------
__global__ void __launch_bounds__(256) k_gemm_z_em(const float* __restrict__ x) {
    int b  = blockIdx.y;
    int l0 = blockIdx.x * 128;
    const float* A  = x + (size_t)b * CC * HWC;            // [c][l]
    const float* Bm = g_mu + (size_t)b * CC * KD;          // [c][k]
    float*       Cz = g_z + (size_t)b * HWC * KD;          // [l][k]

    __shared__ __align__(16) float As[16][128];
    __shared__ __align__(16) float Bs[16][128];

    int tid = threadIdx.x;
    int tx = tid & 15, ty = tid >> 4;
    ull acc2[8][4];
#pragma unroll
    for (int i = 0; i < 8; ++i)
#pragma unroll
        for (int j = 0; j < 4; ++j) acc2[i][j] = 0ull;

    for (int c0 = 0; c0 < CC; c0 += 16) {
#pragma unroll
        for (int i = 0; i < 2; ++i) {
            int lin = tid + i * 256;          // float4 units, 512 total
            int cc  = lin >> 5;
            int p4  = (lin & 31) << 2;
            *(float4*)&As[cc][p4] = *(const float4*)&A[(size_t)(c0 + cc) * HWC + l0 + p4];
            *(float4*)&Bs[cc][p4] = *(const float4*)&Bm[(size_t)(c0 + cc) * KD + p4];
        }
        __syncthreads();
#pragma unroll
        for (int cc = 0; cc < 16; ++cc) {
            float a[8];
            *(float4*)&a[0] = *(float4*)&As[cc][ty * 8];
            *(float4*)&a[4] = *(float4*)&As[cc][ty * 8 + 4];
            ull a2[8];
#pragma unroll
            for (int i = 0; i < 8; ++i) a2[i] = f32x2_pack(a[i], a[i]);
            ull b2[4];
#pragma unroll
            for (int j = 0; j < 4; ++j) b2[j] = *(const ull*)&Bs[cc][tx * 8 + j * 2];
#pragma unroll
            for (int i = 0; i < 8; ++i)
#pragma unroll
                for (int j = 0; j < 4; ++j) f32x2_fma(acc2[i][j], a2[i], b2[j]);
        }
        __syncthreads();
    }

    // unpack, row softmax (16-lane groups share a row), colsum partials
    float acc[8][8];
#pragma unroll
    for (int i = 0; i < 8; ++i)
#pragma unroll
        for (int j = 0; j < 4; ++j)
            f32x2_unpack(acc2[i][j], acc[i][2 * j], acc[i][2 * j + 1]);

    float p[8];
#pragma unroll
    for (int j = 0; j < 8; ++j) p[j] = 0.f;

#pragma unroll
    for (int i = 0; i < 8; ++i) {
        float m = acc[i][0];
#pragma unroll
        for (int j = 1; j < 8; ++j) m = fmaxf(m, acc[i][j]);
#pragma unroll
        for (int o = 8; o; o >>= 1) m = fmaxf(m, __shfl_xor_sync(0xffffffffu, m, o));
        float s = 0.f;
#pragma unroll
        for (int j = 0; j < 8; ++j) { acc[i][j] = __expf(acc[i][j] - m); s += acc[i][j]; }
#pragma unroll
        for (int o = 8; o; o >>= 1) s += __shfl_xor_sync(0xffffffffu, s, o);
        float inv = 1.f / s;
#pragma unroll
        for (int j = 0; j < 8; ++j) { acc[i][j] *= inv; p[j] += acc[i][j]; }
        float* dst = &Cz[(size_t)(l0 + ty * 8 + i) * KD + tx * 8];
        *(float4*)dst       = make_float4(acc[i][0], acc[i][1], acc[i][2], acc[i][3]);
        *(float4*)(dst + 4) = make_float4(acc[i][4], acc[i][5], acc[i][6], acc[i][7]);
    }

    // reduce colsum partials across the 16 ty-groups (reuse As as [16][128])
    float (*cs)[128] = As;
#pragma unroll
    for (int j = 0; j < 8; ++j) cs[ty][tx * 8 + j] = p[j];
    __syncthreads();
    if (tid < 128) {
        float t = 0.f;
#pragma unroll
        for (int w2 = 0; w2 < 16; ++w2) t += cs[w2][tid];
        atomicAdd(&g_colsum[b * KD + tid], t);
    }
}

// ---------------------------------------------------------------------------
// Attention phase: q_z = softmax_k(q . mu), written TRANSPOSED: g_qzt[img][k][hw]
// grid (32, NIMG)
// ---------------------------------------------------------------------------
__global__ void __launch_bounds__(256) k_gemm_z_att(const float* __restrict__ q) {
    int img = blockIdx.y;
    int l0  = blockIdx.x * 128;
    const float* A  = q + (size_t)img * CC * HWC;
    const float* Bm = g_mu + (size_t)(img >> 2) * CC * KD;
    float*       T  = g_qzt + (size_t)img * KD * HWC;      // [k][hw]

    __shared__ __align__(16) float As[16][128];
    __shared__ __align__(16) float Bs[16][128];

    int tid = threadIdx.x;
    int tx = tid & 15, ty = tid >> 4;
    ull acc2[8][4];
#pragma unroll
    for (int i = 0; i < 8; ++i)
#pragma unroll
        for (int j = 0; j < 4; ++j) acc2[i][j] = 0ull;

    for (int c0 = 0; c0 < CC; c0 += 16) {
#pragma unroll
        for (int i = 0; i < 2; ++i) {
            int lin = tid + i * 256;
            int cc  = lin >> 5;
            int p4  = (lin & 31) << 2;
            *(float4*)&As[cc][p4] = *(const float4*)&A[(size_t)(c0 + cc) * HWC + l0 + p4];
            *(float4*)&Bs[cc][p4] = *(const float4*)&Bm[(size_t)(c0 + cc) * KD + p4];
        }
        __syncthreads();
#pragma unroll
        for (int cc = 0; cc < 16; ++cc) {
            float a[8];
            *(float4*)&a[0] = *(float4*)&As[cc][ty * 8];
            *(float4*)&a[4] = *(float4*)&As[cc][ty * 8 + 4];
            ull a2[8];
#pragma unroll
            for (int i = 0; i < 8; ++i) a2[i] = f32x2_pack(a[i], a[i]);
            ull b2[4];
#pragma unroll
            for (int j = 0; j < 4; ++j) b2[j] = *(const ull*)&Bs[cc][tx * 8 + j * 2];
#pragma unroll
            for (int i = 0; i < 8; ++i)
#pragma unroll
                for (int j = 0; j < 4; ++j) f32x2_fma(acc2[i][j], a2[i], b2[j]);
        }
        __syncthreads();
    }

    float acc[8][8];
#pragma unroll
    for (int i = 0; i < 8; ++i)
#pragma unroll
        for (int j = 0; j < 4; ++j)
            f32x2_unpack(acc2[i][j], acc[i][2 * j], acc[i][2 * j + 1]);

#pragma unroll
    for (int i = 0; i < 8; ++i) {
        float m = acc[i][0];
#pragma unroll
        for (int j = 1; j < 8; ++j) m = fmaxf(m, acc[i][j]);
#pragma unroll
        for (int o = 8; o; o >>= 1) m = fmaxf(m, __shfl_xor_sync(0xffffffffu, m, o));
        float s = 0.f;
#pragma unroll
        for (int j = 0; j < 8; ++j) { acc[i][j] = __expf(acc[i][j] - m); s += acc[i][j]; }
#pragma unroll
        for (int o = 8; o; o >>= 1) s += __shfl_xor_sync(0xffffffffu, s, o);
        float inv = 1.f / s;
#pragma unroll
        for (int j = 0; j < 8; ++j) acc[i][j] *= inv;
    }

    // transposed store: row k = tx*8+j, 8 consecutive hw positions (32B sectors)
#pragma unroll
    for (int j = 0; j < 8; ++j) {
        float* dst = &T[(size_t)(tx * 8 + j) * HWC + l0 + ty * 8];
        *(float4*)dst       = make_float4(acc[0][j], acc[1][j], acc[2][j], acc[3][j]);
        *(float4*)(dst + 4) = make_float4(acc[4][j], acc[5][j], acc[6][j], acc[7][j]);
    }
}

// ---------------------------------------------------------------------------
// mu_acc[b][c][k] += sum_{l in chunk} x[b][c][l] * z[b][l][k]/(EPS+colsum[b][k])
// Split over l (8 chunks of 512). BM=64(c), BN=128(k), BK=32(l).
// grid: (CC/64, 8, B), 256 threads, 4x8 per thread.
// ---------------------------------------------------------------------------
__global__ void __launch_bounds__(256) k_gemm_mu(const float* __restrict__ x) {
    int b  = blockIdx.z;
    int c0 = blockIdx.x * 64;
    int l0 = blockIdx.y * 512;
    const float* A    = x + (size_t)b * CC * HWC;          // [c][l]
    const float* Bsrc = g_z + (size_t)b * HWC * KD;        // [l][k]

    __shared__ __align__(16) float As[32][68];   // [l][c] transposed (+pad)
    __shared__ __align__(16) float Bs[32][128];  // [l][k]
    __shared__ float invcs[128];

    int tid = threadIdx.x;
    if (tid < 128) invcs[tid] = 1.f / (EPSF + g_colsum[b * KD + tid]);
    __syncthreads();

    int tx = tid & 15, ty = tid >> 4;
    ull acc2[4][4];
#pragma unroll
    for (int i = 0; i < 4; ++i)
#pragma unroll
        for (int j = 0; j < 4; ++j) acc2[i][j] = 0ull;

    for (int lb = 0; lb < 512; lb += 32) {
#pragma unroll
        for (int i = 0; i < 2; ++i) {                  // A: 64c x 32l -> [l][c]
            int lin = tid + i * 256;                   // float4 units, 512
            int cc  = lin >> 3;
            int l4  = (lin & 7) << 2;
            float4 va = *(const float4*)&A[(size_t)(c0 + cc) * HWC + l0 + lb + l4];
            As[l4 + 0][cc] = va.x; As[l4 + 1][cc] = va.y;
            As[l4 + 2][cc] = va.z; As[l4 + 3][cc] = va.w;
        }
#pragma unroll
        for (int i = 0; i < 4; ++i) {                  // B: 32l x 128k, scaled
            int lin = tid + i * 256;                   // float4 units, 1024
            int ll  = lin >> 5;
            int k4  = (lin & 31) << 2;
            float4 vb = *(const float4*)&Bsrc[(size_t)(l0 + lb + ll) * KD + k4];
            vb.x *= invcs[k4]; vb.y *= invcs[k4 + 1];
            vb.z *= invcs[k4 + 2]; vb.w *= invcs[k4 + 3];
            *(float4*)&Bs[ll][k4] = vb;
        }
        __syncthreads();
#pragma unroll
        for (int ll = 0; ll < 32; ++ll) {
            float a[4];
            *(float4*)&a[0] = *(float4*)&As[ll][ty * 4];
            ull a2[4];
#pragma unroll
            for (int i = 0; i < 4; ++i) a2[i] = f32x2_pack(a[i], a[i]);
            ull b2[4];
#pragma unroll
            for (int j = 0; j < 4; ++j) b2[j] = *(const ull*)&Bs[ll][tx * 8 + j * 2];
#pragma unroll
            for (int i = 0; i < 4; ++i)
#pragma unroll
                for (int j = 0; j < 4; ++j) f32x2_fma(acc2[i][j], a2[i], b2[j]);
        }
        __syncthreads();
    }
#pragma unroll
    for (int i = 0; i < 4; ++i)
#pragma unroll
        for (int j = 0; j < 4; ++j) {
            float v0, v1;
            f32x2_unpack(acc2[i][j], v0, v1);
            size_t base = (size_t)b * CC * KD + (size_t)(c0 + ty * 4 + i) * KD + tx * 8 + j * 2;
            atomicAdd(&g_mu_acc[base],     v0);
            atomicAdd(&g_mu_acc[base + 1], v1);
        }
}

// ---------------------------------------------------------------------------
// l2-normalize mu over c: mu[b][c][k] = acc/(EPS + ||acc[b][:][k]||)
// ---------------------------------------------------------------------------
__global__ void __launch_bounds__(256) k_l2norm() {
    int gw = blockIdx.x * 8 + (threadIdx.x >> 5);   // 0..511
    int lane = threadIdx.x & 31;
    int b = gw >> 7;
    int k = gw & 127;
    float v[8];
    float ss = 0.f;
#pragma unroll
    for (int i = 0; i < 8; ++i) {
        v[i] = g_mu_acc[(size_t)(b * CC + lane + i * 32) * KD + k];
        ss += v[i] * v[i];
    }
#pragma unroll
    for (int o = 16; o; o >>= 1) ss += __shfl_xor_sync(0xffffffffu, ss, o);
    float inv = 1.f / (EPSF + sqrtf(ss));
#pragma unroll
    for (int i = 0; i < 8; ++i)
        g_mu[(size_t)(b * CC + lane + i * 32) * KD + k] = v[i] * inv;
}

// ---------------------------------------------------------------------------
// Fold mu into the rec-half of the conv weights:
//   wfold[b][oc][k][tap] = sum_c w[oc][256+c][tap] * mu[b][c][k]
// grid (OCH, BB), 128 threads (one per k). ~0.6 GF total.
// ---------------------------------------------------------------------------
__global__ void __launch_bounds__(128) k_fold_w(const float* __restrict__ w) {
    int oc = blockIdx.x;
    int b  = blockIdx.y;
    int k  = threadIdx.x;
    float acc[9];
#pragma unroll
    for (int t = 0; t < 9; ++t) acc[t] = 0.f;
    const float* wbase = w + ((size_t)oc * IC2 + CC) * 9;
    const float* mubase = g_mu + (size_t)b * CC * KD + k;
    for (int c = 0; c < CC; ++c) {
        float m = mubase[(size_t)c * KD];
        const float* wr = wbase + (size_t)c * 9;
#pragma unroll
        for (int t = 0; t < 9; ++t) acc[t] = fmaf(m, __ldg(&wr[t]), acc[t]);
    }
    float* dst = g_wfold + (((size_t)b * OCH + oc) * KD + k) * 9;
#pragma unroll
    for (int t = 0; t < 9; ++t) dst[t] = acc[t];
}

// ---------------------------------------------------------------------------
// 3x3 SAME conv over 384 effective input channels:
//   ic <  256: querys channel ic, weights from conv_w
//   ic >= 256: q_z^T channel (ic-256), weights from g_wfold[b]
// Block: 1 img, 4 rows x 64 cols (256 pos), 128 oc. 512 threads.
// Thread: 8 cols x 8 oc with f32x2-packed FMAs. grid: (16, 2, 16)
// ---------------------------------------------------------------------------
#define CBKC 4
__global__ void __launch_bounds__(512) k_conv(const float* __restrict__ q,
                                              const float* __restrict__ w,
                                              const float* __restrict__ bias,
                                              float* __restrict__ out) {
    int img = blockIdx.z;
    int b   = img >> 2;
    int ocb = blockIdx.y * 128;
    int r0  = blockIdx.x * 4;

    __shared__ __align__(16) float in_s[CBKC][6][68];    // rows -1..+4, cols -1..64 (+pad)
    __shared__ __align__(16) float w_s[CBKC][9][132];    // [ic][tap][oc] (+pad)

    int tid  = threadIdx.x;
    int tx   = tid & 15;           // oc group: oc = ocb + tx*8 + j
    int tp   = tid >> 4;           // 0..31
    int prow = tp >> 3;            // 0..3
    int pcol = (tp & 7) * 8;       // 0..56

    ull acc2[8][4];
#pragma unroll
    for (int i = 0; i < 8; ++i)
#pragma unroll
        for (int j = 0; j < 4; ++j) acc2[i][j] = 0ull;

    const float* qimg = q + (size_t)img * CC * HWC;
    const float* zimg = g_qzt + (size_t)img * KD * HWC;
    const float* wfold = g_wfold + (size_t)b * OCH * KD * 9;

    for (int icb = 0; icb < ICEFF; icb += CBKC) {
        const float* src = (icb < CC) ? (qimg + (size_t)icb * HWC)
                                      : (zimg + (size_t)(icb - CC) * HWC);
        // input patch: CBKC ic x 6 rows x 66 cols (zero-padded halo)
        for (int lin = tid; lin < CBKC * 6 * 68; lin += 512) {
            int ic = lin / (6 * 68);
            int rr = (lin / 68) % 6;
            int cc = lin % 68;
            int y  = r0 - 1 + rr;
            int xx = cc - 1;
            float v = 0.f;
            if (cc < 66 && (unsigned)y < 64u && (unsigned)xx < 64u)
                v = src[(size_t)ic * HWC + y * 64 + xx];
            in_s[ic][rr][cc] = v;
        }
        // weights: 128 oc x CBKC ic x 9 taps
        for (int lin = tid; lin < 128 * CBKC * 9; lin += 512) {
            int oc  = lin / (CBKC * 9);
            int r   = lin % (CBKC * 9);
            int ic  = r / 9;
            int tap = r % 9;
            float wv;
            if (icb < CC)
                wv = w[(size_t)(ocb + oc) * IC2 * 9 + (size_t)(icb + ic) * 9 + tap];
            else
                wv = wfold[((size_t)(ocb + oc) * KD + (icb - CC + ic)) * 9 + tap];
            w_s[ic][tap][oc] = wv;
        }
        __syncthreads();
#pragma unroll
        for (int ic = 0; ic < CBKC; ++ic) {
#pragma unroll
            for (int ky = 0; ky < 3; ++ky) {
                float a10[10];
#pragma unroll
                for (int t = 0; t < 10; ++t) a10[t] = in_s[ic][prow + ky][pcol + t];
                ull a2[10];
#pragma unroll
                for (int t = 0; t < 10; ++t) a2[t] = f32x2_pack(a10[t], a10[t]);
#pragma unroll
                for (int kx = 0; kx < 3; ++kx) {
                    ull b2[4];
#pragma unroll
                    for (int j = 0; j < 4; ++j)
                        b2[j] = *(const ull*)&w_s[ic][ky * 3 + kx][tx * 8 + j * 2];
#pragma unroll
                    for (int i = 0; i < 8; ++i)
#pragma unroll
                        for (int j = 0; j < 4; ++j)
                            f32x2_fma(acc2[i][j], a2[kx + i], b2[j]);
                }
            }
        }
        __syncthreads();
    }
    // epilogue: unpack + bias, 8 contiguous floats per oc row
#pragma unroll
    for (int jj = 0; jj < 4; ++jj) {
        float v0[8], v1[8];
#pragma unroll
        for (int i = 0; i < 8; ++i) f32x2_unpack(acc2[i][jj], v0[i], v1[i]);
#pragma unroll
        for (int s = 0; s < 2; ++s) {
            int oc = ocb + tx * 8 + jj * 2 + s;
            float bv = bias[oc];
            const float* v = s ? v1 : v0;
            float* dst = out + ((size_t)img * OCH + oc) * HWC + (r0 + prow) * 64 + pcol;
            *(float4*)dst       = make_float4(v[0] + bv, v[1] + bv, v[2] + bv, v[3] + bv);
            *(float4*)(dst + 4) = make_float4(v[4] + bv, v[5] + bv, v[6] + bv, v[7] + bv);
        }
    }
}

__global__ void k_copy_mu(float* __restrict__ out_mu) {
    int i = blockIdx.x * blockDim.x + threadIdx.x;
    if (i < BB * CC * KD) out_mu[i] = g_mu[i];
}

// ---------------------------------------------------------------------------
// launch
// ---------------------------------------------------------------------------
extern "C" void kernel_launch(void* const* d_in, const int* in_sizes, int n_in,
                              void* d_out, int out_size) {
    const float* x      = (const float*)d_in[0];   // [4,256,64,64]
    const float* querys = (const float*)d_in[1];   // [16,256,64,64]
    const float* mu0    = (const float*)d_in[2];   // [1,256,128]
    const float* conv_w = (const float*)d_in[3];   // [256,512,3,3]
    const float* conv_b = (const float*)d_in[4];   // [256]
    float* out    = (float*)d_out;
    float* out_mu = out + (size_t)NIMG * OCH * HWC;

    (void)in_sizes; (void)n_in; (void)out_size;

    k_init_mu<<<(BB * CC * KD + 255) / 256, 256>>>(mu0);

    // EM iterations: fused gemm+softmax+colsum, then mu update + l2norm
    for (int it = 0; it < STAGE_NUM; ++it) {
        k_zero_acc<<<(BB * CC * KD + 255) / 256, 256>>>();
        k_gemm_z_em<<<dim3(HWC / 128, BB), 256>>>(x);
        k_gemm_mu<<<dim3(CC / 64, 8, BB), 256>>>(x);
        k_l2norm<<<64, 256>>>();
    }

    // attention: q_z (softmax fused, written transposed [k][hw])
    k_gemm_z_att<<<dim3(HWC / 128, NIMG), 256>>>(querys);

    // fold mu into the rec-half of the conv weights
    k_fold_w<<<dim3(OCH, BB), 128>>>(conv_w);

    // conv over 384 effective channels (querys ++ folded q_z^T) + bias
    k_conv<<<dim3(16, 2, NIMG), 512>>>(querys, conv_w, conv_b, out);

    // second output: mu
    k_copy_mu<<<(BB * CC * KD + 255) / 256, 256>>>(out_mu);
}

// round 16
// speedup vs baseline: 1.3511x; 1.3511x over previous
#include <cuda_runtime.h>

// Problem constants (fixed shapes from setup_inputs)
#define BB        4
#define NIMG      16      // b*n
#define CC        256
#define HWC       4096    // 64*64
#define KD        128
#define OCH       256
#define IC2       512
#define ICEFF     384     // 256 query channels + 128 folded k-channels
#define EPSF      1e-6f
#define STAGE_NUM 5

typedef unsigned long long ull;

// ---------------------------------------------------------------------------
// f32x2 packed-FMA helpers (sm_100+): 2 fp32 FMAs per instruction, bit-exact.
// ---------------------------------------------------------------------------
__device__ __forceinline__ ull f32x2_pack(float x, float y) {
    ull r;
    asm("mov.b64 %0, {%1, %2};" : "=l"(r)
        : "r"(__float_as_uint(x)), "r"(__float_as_uint(y)));
    return r;
}
__device__ __forceinline__ void f32x2_fma(ull& d, ull a, ull b) {
    asm("fma.rn.f32x2 %0, %1, %2, %0;" : "+l"(d) : "l"(a), "l"(b));
}
__device__ __forceinline__ void f32x2_unpack(ull v, float& x, float& y) {
    unsigned lo, hi;
    asm("mov.b64 {%0, %1}, %2;" : "=r"(lo), "=r"(hi) : "l"(v));
    x = __uint_as_float(lo);
    y = __uint_as_float(hi);
}
__device__ __forceinline__ void cpa16(unsigned dst, const float* src) {
    asm volatile("cp.async.cg.shared.global [%0], [%1], 16;" :: "r"(dst), "l"(src));
}

// ---------------------------------------------------------------------------
// Device scratch (no cudaMalloc allowed)
// ---------------------------------------------------------------------------
__device__ float g_mu[BB * CC * KD];              // current mu   [b][c][k]
__device__ float g_mu_acc[BB * CC * KD];          // accumulation [b][c][k]
__device__ float g_colsum[BB * KD];               // softmax col sums [b][k]
__device__ float g_z[(size_t)BB * HWC * KD];      // EM z  [b][l][k]   (8 MB)
__device__ float g_qzt[(size_t)NIMG * KD * HWC];  // q_z^T [img][k][hw] (32 MB)
__device__ float g_wq[(size_t)CC * 9 * OCH];      // conv_w query half  [ic][tap][oc]
__device__ float g_wf2[(size_t)BB * KD * 9 * OCH];// folded weights [b][k][tap][oc]

// ---------------------------------------------------------------------------
// init mu (broadcast mu0) + zero accumulators
// ---------------------------------------------------------------------------
__global__ void k_init_mu(const float* __restrict__ mu0) {
    int i = blockIdx.x * blockDim.x + threadIdx.x;
    if (i < BB * CC * KD) { g_mu[i] = mu0[i % (CC * KD)]; g_mu_acc[i] = 0.f; }
    if (i < BB * KD)      g_colsum[i] = 0.f;
}

// transpose query-half conv weights once: g_wq[ic][tap][oc] = w[oc][ic][tap]
__global__ void __launch_bounds__(256) k_wq(const float* __restrict__ w) {
    int ic = blockIdx.x;
    int oc = threadIdx.x;
#pragma unroll
    for (int t = 0; t < 9; ++t)
        g_wq[((size_t)ic * 9 + t) * OCH + oc] = w[((size_t)oc * IC2 + ic) * 9 + t];
}

// ---------------------------------------------------------------------------
// EM phase: z[b][l][k] = softmax_k( sum_c x[b][c][l] * mu[b][c][k] )
// Fused softmax + colsum accumulation. Tile 128(l) x 128(k) x 16(c).
// Thread columns are k = j*32 + tx*2 + {0,1}  (conflict-free LDS.64).
// ---------------------------------------------------------------------------
__global__ void __launch_bounds__(256) k_gemm_z_em(const float* __restrict__ x) {
    int b  = blockIdx.y;
    int l0 = blockIdx.x * 128;
    const float* A  = x + (size_t)b * CC * HWC;            // [c][l]
    const float* Bm = g_mu + (size_t)b * CC * KD;          // [c][k]
    float*       Cz = g_z + (size_t)b * HWC * KD;          // [l][k]

    __shared__ __align__(16) float As[16][128];
    __shared__ __align__(16) float Bs[16][128];

    int tid = threadIdx.x;
    int tx = tid & 15, ty = tid >> 4;
    ull acc2[8][4];
#pragma unroll
    for (int i = 0; i < 8; ++i)
#pragma unroll
        for (int j = 0; j < 4; ++j) acc2[i][j] = 0ull;

    for (int c0 = 0; c0 < CC; c0 += 16) {
#pragma unroll
        for (int i = 0; i < 2; ++i) {
            int lin = tid + i * 256;          // float4 units, 512 total
            int cc  = lin >> 5;
            int p4  = (lin & 31) << 2;
            *(float4*)&As[cc][p4] = *(const float4*)&A[(size_t)(c0 + cc) * HWC + l0 + p4];
            *(float4*)&Bs[cc][p4] = *(const float4*)&Bm[(size_t)(c0 + cc) * KD + p4];
        }
        __syncthreads();
#pragma unroll
        for (int cc = 0; cc < 16; ++cc) {
            float a[8];
            *(float4*)&a[0] = *(float4*)&As[cc][ty * 8];
            *(float4*)&a[4] = *(float4*)&As[cc][ty * 8 + 4];
            ull a2[8];
#pragma unroll
            for (int i = 0; i < 8; ++i) a2[i] = f32x2_pack(a[i], a[i]);
            ull b2[4];
#pragma unroll
            for (int j = 0; j < 4; ++j) b2[j] = *(const ull*)&Bs[cc][j * 32 + tx * 2];
#pragma unroll
            for (int i = 0; i < 8; ++i)
#pragma unroll
                for (int j = 0; j < 4; ++j) f32x2_fma(acc2[i][j], a2[i], b2[j]);
        }
        __syncthreads();
    }

    // unpack: column m=2j+s  <->  k = j*32 + tx*2 + s
    float acc[8][8];
#pragma unroll
    for (int i = 0; i < 8; ++i)
#pragma unroll
        for (int j = 0; j < 4; ++j)
            f32x2_unpack(acc2[i][j], acc[i][2 * j], acc[i][2 * j + 1]);

    float p[8];
#pragma unroll
    for (int m = 0; m < 8; ++m) p[m] = 0.f;

#pragma unroll
    for (int i = 0; i < 8; ++i) {
        float mx = acc[i][0];
#pragma unroll
        for (int m = 1; m < 8; ++m) mx = fmaxf(mx, acc[i][m]);
#pragma unroll
        for (int o = 8; o; o >>= 1) mx = fmaxf(mx, __shfl_xor_sync(0xffffffffu, mx, o));
        float s = 0.f;
#pragma unroll
        for (int m = 0; m < 8; ++m) { acc[i][m] = __expf(acc[i][m] - mx); s += acc[i][m]; }
#pragma unroll
        for (int o = 8; o; o >>= 1) s += __shfl_xor_sync(0xffffffffu, s, o);
        float inv = 1.f / s;
#pragma unroll
        for (int m = 0; m < 8; ++m) { acc[i][m] *= inv; p[m] += acc[i][m]; }
        float* dst = &Cz[(size_t)(l0 + ty * 8 + i) * KD + tx * 2];
#pragma unroll
        for (int j = 0; j < 4; ++j)
            *(float2*)(dst + j * 32) = make_float2(acc[i][2 * j], acc[i][2 * j + 1]);
    }

    // reduce colsum partials across the 16 ty-groups (reuse As as [16][128])
    float (*cs)[128] = As;
#pragma unroll
    for (int j = 0; j < 4; ++j) {
        cs[ty][j * 32 + tx * 2]     = p[2 * j];
        cs[ty][j * 32 + tx * 2 + 1] = p[2 * j + 1];
    }
    __syncthreads();
    if (tid < 128) {
        float t = 0.f;
#pragma unroll
        for (int w2 = 0; w2 < 16; ++w2) t += cs[w2][tid];
        atomicAdd(&g_colsum[b * KD + tid], t);
    }
}

// ---------------------------------------------------------------------------
// Attention phase: q_z = softmax_k(q . mu), written TRANSPOSED: g_qzt[img][k][hw]
// ---------------------------------------------------------------------------
__global__ void __launch_bounds__(256) k_gemm_z_att(const float* __restrict__ q) {
    int img = blockIdx.y;
    int l0  = blockIdx.x * 128;
    const float* A  = q + (size_t)img * CC * HWC;
    const float* Bm = g_mu + (size_t)(img >> 2) * CC * KD;
    float*       T  = g_qzt + (size_t)img * KD * HWC;      // [k][hw]

    __shared__ __align__(16) float As[16][128];
    __shared__ __align__(16) float Bs[16][128];

    int tid = threadIdx.x;
    int tx = tid & 15, ty = tid >> 4;
    ull acc2[8][4];
#pragma unroll
    for (int i = 0; i < 8; ++i)
#pragma unroll
        for (int j = 0; j < 4; ++j) acc2[i][j] = 0ull;

    for (int c0 = 0; c0 < CC; c0 += 16) {
#pragma unroll
        for (int i = 0; i < 2; ++i) {
            int lin = tid + i * 256;
            int cc  = lin >> 5;
            int p4  = (lin & 31) << 2;
            *(float4*)&As[cc][p4] = *(const float4*)&A[(size_t)(c0 + cc) * HWC + l0 + p4];
            *(float4*)&Bs[cc][p4] = *(const float4*)&Bm[(size_t)(c0 + cc) * KD + p4];
        }
        __syncthreads();
#pragma unroll
        for (int cc = 0; cc < 16; ++cc) {
            float a[8];
            *(float4*)&a[0] = *(float4*)&As[cc][ty * 8];
            *(float4*)&a[4] = *(float4*)&As[cc][ty * 8 + 4];
            ull a2[8];
#pragma unroll
            for (int i = 0; i < 8; ++i) a2[i] = f32x2_pack(a[i], a[i]);
            ull b2[4];
#pragma unroll
            for (int j = 0; j < 4; ++j) b2[j] = *(const ull*)&Bs[cc][j * 32 + tx * 2];
#pragma unroll
            for (int i = 0; i < 8; ++i)
#pragma unroll
                for (int j = 0; j < 4; ++j) f32x2_fma(acc2[i][j], a2[i], b2[j]);
        }
        __syncthreads();
    }

    float acc[8][8];
#pragma unroll
    for (int i = 0; i < 8; ++i)
#pragma unroll
        for (int j = 0; j < 4; ++j)
            f32x2_unpack(acc2[i][j], acc[i][2 * j], acc[i][2 * j + 1]);

#pragma unroll
    for (int i = 0; i < 8; ++i) {
        float mx = acc[i][0];
#pragma unroll
        for (int m = 1; m < 8; ++m) mx = fmaxf(mx, acc[i][m]);
#pragma unroll
        for (int o = 8; o; o >>= 1) mx = fmaxf(mx, __shfl_xor_sync(0xffffffffu, mx, o));
        float s = 0.f;
#pragma unroll
        for (int m = 0; m < 8; ++m) { acc[i][m] = __expf(acc[i][m] - mx); s += acc[i][m]; }
#pragma unroll
        for (int o = 8; o; o >>= 1) s += __shfl_xor_sync(0xffffffffu, s, o);
        float inv = 1.f / s;
#pragma unroll
        for (int m = 0; m < 8; ++m) acc[i][m] *= inv;
    }

    // transposed store: row k = j*32 + tx*2 + s, 8 consecutive hw positions
#pragma unroll
    for (int m = 0; m < 8; ++m) {
        int k = (m >> 1) * 32 + tx * 2 + (m & 1);
        float* dst = &T[(size_t)k * HWC + l0 + ty * 8];
        *(float4*)dst       = make_float4(acc[0][m], acc[1][m], acc[2][m], acc[3][m]);
        *(float4*)(dst + 4) = make_float4(acc[4][m], acc[5][m], acc[6][m], acc[7][m]);
    }
}

// ---------------------------------------------------------------------------
// mu_acc[b][c][k] += sum_{l in chunk} x[b][c][l] * z[b][l][k]/(EPS+colsum[b][k])
// Split over l (16 chunks of 256). BM=64(c), BN=128(k), BK=32(l).
// grid: (4, 16, B), 256 threads, 4x8 per thread.
// ---------------------------------------------------------------------------
__global__ void __launch_bounds__(256) k_gemm_mu(const float* __restrict__ x) {
    int b  = blockIdx.z;
    int c0 = blockIdx.x * 64;
    int l0 = blockIdx.y * 256;
    const float* A    = x + (size_t)b * CC * HWC;          // [c][l]
    const float* Bsrc = g_z + (size_t)b * HWC * KD;        // [l][k]

    __shared__ __align__(16) float As[32][68];   // [l][c] transposed (+pad)
    __shared__ __align__(16) float Bs[32][128];  // [l][k]
    __shared__ float invcs[128];

    int tid = threadIdx.x;
    if (tid < 128) invcs[tid] = 1.f / (EPSF + g_colsum[b * KD + tid]);
    __syncthreads();

    int tx = tid & 15, ty = tid >> 4;
    ull acc2[4][4];
#pragma unroll
    for (int i = 0; i < 4; ++i)
#pragma unroll
        for (int j = 0; j < 4; ++j) acc2[i][j] = 0ull;

    for (int lb = 0; lb < 256; lb += 32) {
#pragma unroll
        for (int i = 0; i < 2; ++i) {                  // A: 64c x 32l -> [l][c]
            int lin = tid + i * 256;                   // float4 units, 512
            int cc  = lin >> 3;
            int l4  = (lin & 7) << 2;
            float4 va = *(const float4*)&A[(size_t)(c0 + cc) * HWC + l0 + lb + l4];
            As[l4 + 0][cc] = va.x; As[l4 + 1][cc] = va.y;
            As[l4 + 2][cc] = va.z; As[l4 + 3][cc] = va.w;
        }
#pragma unroll
        for (int i = 0; i < 4; ++i) {                  // B: 32l x 128k, scaled
            int lin = tid + i * 256;                   // float4 units, 1024
            int ll  = lin >> 5;
            int k4  = (lin & 31) << 2;
            float4 vb = *(const float4*)&Bsrc[(size_t)(l0 + lb + ll) * KD + k4];
            vb.x *= invcs[k4]; vb.y *= invcs[k4 + 1];
            vb.z *= invcs[k4 + 2]; vb.w *= invcs[k4 + 3];
            *(float4*)&Bs[ll][k4] = vb;
        }
        __syncthreads();
#pragma unroll
        for (int ll = 0; ll < 32; ++ll) {
            float a[4];
            *(float4*)&a[0] = *(float4*)&As[ll][ty * 4];
            ull a2[4];
#pragma unroll
            for (int i = 0; i < 4; ++i) a2[i] = f32x2_pack(a[i], a[i]);
            ull b2[4];
#pragma unroll
            for (int j = 0; j < 4; ++j) b2[j] = *(const ull*)&Bs[ll][j * 32 + tx * 2];
#pragma unroll
            for (int i = 0; i < 4; ++i)
#pragma unroll
                for (int j = 0; j < 4; ++j) f32x2_fma(acc2[i][j], a2[i], b2[j]);
        }
        __syncthreads();
    }
#pragma unroll
    for (int i = 0; i < 4; ++i)
#pragma unroll
        for (int j = 0; j < 4; ++j) {
            float v0, v1;
            f32x2_unpack(acc2[i][j], v0, v1);
            size_t base = (size_t)b * CC * KD + (size_t)(c0 + ty * 4 + i) * KD + j * 32 + tx * 2;
            atomicAdd(&g_mu_acc[base],     v0);
            atomicAdd(&g_mu_acc[base + 1], v1);
        }
}

// ---------------------------------------------------------------------------
// l2-normalize mu over c + zero accumulators for the next iteration
// ---------------------------------------------------------------------------
__global__ void __launch_bounds__(256) k_l2norm() {
    int gw = blockIdx.x * 8 + (threadIdx.x >> 5);   // 0..511
    int lane = threadIdx.x & 31;
    int b = gw >> 7;
    int k = gw & 127;
    float v[8];
    float ss = 0.f;
#pragma unroll
    for (int i = 0; i < 8; ++i) {
        size_t idx = (size_t)(b * CC + lane + i * 32) * KD + k;
        v[i] = g_mu_acc[idx];
        g_mu_acc[idx] = 0.f;
        ss += v[i] * v[i];
    }
#pragma unroll
    for (int o = 16; o; o >>= 1) ss += __shfl_xor_sync(0xffffffffu, ss, o);
    float inv = 1.f / (EPSF + sqrtf(ss));
#pragma unroll
    for (int i = 0; i < 8; ++i)
        g_mu[(size_t)(b * CC + lane + i * 32) * KD + k] = v[i] * inv;
    if (lane == 0) g_colsum[b * KD + k] = 0.f;
}

// ---------------------------------------------------------------------------
// Fold mu into the rec-half of the conv weights, output layout [b][k][tap][oc]:
//   wf2[b][k][tap][oc] = sum_c w[oc][256+c][tap] * mu[b][c][k]
// grid (OCH, BB), 128 threads (one per k).
// ---------------------------------------------------------------------------
__global__ void __launch_bounds__(128) k_fold_w(const float* __restrict__ w) {
    int oc = blockIdx.x;
    int b  = blockIdx.y;
    int k  = threadIdx.x;
    float acc[9];
#pragma unroll
    for (int t = 0; t < 9; ++t) acc[t] = 0.f;
    const float* wbase = w + ((size_t)oc * IC2 + CC) * 9;
    const float* mubase = g_mu + (size_t)b * CC * KD + k;
    for (int c = 0; c < CC; ++c) {
        float m = mubase[(size_t)c * KD];
        const float* wr = wbase + (size_t)c * 9;
#pragma unroll
        for (int t = 0; t < 9; ++t) acc[t] = fmaf(m, __ldg(&wr[t]), acc[t]);
    }
#pragma unroll
    for (int t = 0; t < 9; ++t)
        g_wf2[(((size_t)b * KD + k) * 9 + t) * OCH + oc] = acc[t];
}

// ---------------------------------------------------------------------------
// 3x3 SAME conv over 384 effective input channels, double-buffered cp.async:
//   ic <  256: querys channel ic, weights from g_wq  [ic][tap][oc]
//   ic >= 256: q_z^T channel (ic-256), weights from g_wf2[b] [k][tap][oc]
// Block: 1 img, 4 rows x 64 cols (256 pos), 128 oc. 512 threads.
// Thread: 8 cols x 8 oc (oc = ocb + j*32 + tx*2 + s) with f32x2 FMAs.
// dyn smem: in[2][4][6][68] (halo pre-zeroed) + w[2][36][128]. grid (16,2,16)
// ---------------------------------------------------------------------------
#define CBKC      4
#define NCHUNK    (ICEFF / CBKC)     // 96
#define INS_FLT   (2 * CBKC * 6 * 68)      // 3264
#define WS_FLT    (2 * 36 * 128)           // 9216
#define CONV_SMEM ((INS_FLT + WS_FLT) * 4) // 49920 B

__global__ void __launch_bounds__(512) k_conv(const float* __restrict__ q,
                                              const float* __restrict__ bias,
                                              float* __restrict__ out) {
    extern __shared__ __align__(16) float smemf[];
    float* insf = smemf;             // [2][4][6][68]
    float* wsf  = smemf + INS_FLT;   // [2][36][128]
    unsigned sb;
    asm("{ .reg .u64 t; cvta.to.shared.u64 t, %1; cvt.u32.u64 %0, t; }"
        : "=r"(sb) : "l"(smemf));
    unsigned sb_w = sb + INS_FLT * 4;

    int img = blockIdx.z;
    int b   = img >> 2;
    int ocb = blockIdx.y * 128;
    int r0  = blockIdx.x * 4;

    int tid  = threadIdx.x;
    int tx   = tid & 15;           // oc = ocb + j*32 + tx*2 + s
    int tp   = tid >> 4;           // 0..31
    int prow = tp >> 3;            // 0..3
    int pcol = (tp & 7) * 8;       // 0..56

    const float* qimg   = q + (size_t)img * CC * HWC;
    const float* zimg   = g_qzt + (size_t)img * KD * HWC;
    const float* wfoldb = g_wf2 + (size_t)b * KD * 9 * OCH;

    // zero input staging (halo cols / OOB rows stay zero forever)
    for (int i = tid; i < INS_FLT; i += 512) insf[i] = 0.f;
    __syncthreads();

    // ---- chunk issue: 384 input cp.asyncs + 1152 weight cp.asyncs (16B) ----
    auto issue = [&](int buf, int chunk) {
        int icb = chunk * CBKC;
        const float* srcp = (icb < CC) ? qimg + (size_t)icb * HWC
                                       : zimg + (size_t)(icb - CC) * HWC;
        const float* wsrc = (icb < CC) ? g_wq + (size_t)icb * 9 * OCH
                                       : wfoldb + (size_t)(icb - CC) * 9 * OCH;
#pragma unroll
        for (int kk = 0; kk < 3; ++kk) {
            int op = tid + kk * 512;
            if (op < 384) {
                int ic  = op / 96;
                int rr  = (op / 16) % 6;
                int seg = op & 15;
                int y   = r0 - 1 + rr;
                if ((unsigned)y < 64u)
                    cpa16(sb + (((buf * CBKC + ic) * 6 + rr) * 68 + 4 + seg * 4) * 4,
                          srcp + (size_t)ic * HWC + y * 64 + seg * 4);
            } else {
                int wop = op - 384;          // 0..1151
                int row = wop >> 5;          // ic*9+tap, 0..35
                int seg = wop & 31;
                cpa16(sb_w + ((buf * 36 + row) * 128 + seg * 4) * 4,
                      wsrc + (size_t)row * OCH + ocb + seg * 4);
            }
        }
        asm volatile("cp.async.commit_group;" ::: "memory");
    };

    ull acc2[8][4];
#pragma unroll
    for (int i = 0; i < 8; ++i)
#pragma unroll
        for (int j = 0; j < 4; ++j) acc2[i][j] = 0ull;

    issue(0, 0);
    asm volatile("cp.async.wait_group 0;" ::: "memory");
    __syncthreads();

    int buf = 0;
    for (int chunk = 0; chunk < NCHUNK; ++chunk) {
        if (chunk + 1 < NCHUNK) issue(buf ^ 1, chunk + 1);
        // compute on buf
#pragma unroll
        for (int ic = 0; ic < CBKC; ++ic) {
            int ib = (buf * CBKC + ic) * 6;
#pragma unroll
            for (int ky = 0; ky < 3; ++ky) {
                const float* rowp = insf + (ib + prow + ky) * 68 + 3 + pcol;
                float a10[10];
#pragma unroll
                for (int t = 0; t < 10; ++t) a10[t] = rowp[t];
                ull a2[10];
#pragma unroll
                for (int t = 0; t < 10; ++t) a2[t] = f32x2_pack(a10[t], a10[t]);
#pragma unroll
                for (int kx = 0; kx < 3; ++kx) {
                    const ull* wp = (const ull*)(wsf + (buf * 36 + ic * 9 + ky * 3 + kx) * 128 + tx * 2);
                    ull b2[4];
#pragma unroll
                    for (int j = 0; j < 4; ++j) b2[j] = wp[j * 16];
#pragma unroll
                    for (int i = 0; i < 8; ++i)
#pragma unroll
                        for (int j = 0; j < 4; ++j)
                            f32x2_fma(acc2[i][j], a2[kx + i], b2[j]);
                }
            }
        }
        if (chunk + 1 < NCHUNK)
            asm volatile("cp.async.wait_group 0;" ::: "memory");
        __syncthreads();
        buf ^= 1;
    }

    // epilogue: unpack + bias; oc = ocb + j*32 + tx*2 + s
#pragma unroll
    for (int j = 0; j < 4; ++j) {
        float v0[8], v1[8];
#pragma unroll
        for (int i = 0; i < 8; ++i) f32x2_unpack(acc2[i][j], v0[i], v1[i]);
#pragma unroll
        for (int s = 0; s < 2; ++s) {
            int oc = ocb + j * 32 + tx * 2 + s;
            float bv = bias[oc];
            const float* v = s ? v1 : v0;
            float* dst = out + ((size_t)img * OCH + oc) * HWC + (r0 + prow) * 64 + pcol;
            *(float4*)dst       = make_float4(v[0] + bv, v[1] + bv, v[2] + bv, v[3] + bv);
            *(float4*)(dst + 4) = make_float4(v[4] + bv, v[5] + bv, v[6] + bv, v[7] + bv);
        }
    }
}

__global__ void k_copy_mu(float* __restrict__ out_mu) {
    int i = blockIdx.x * blockDim.x + threadIdx.x;
    if (i < BB * CC * KD) out_mu[i] = g_mu[i];
}

// ---------------------------------------------------------------------------
// launch
// ---------------------------------------------------------------------------
extern "C" void kernel_launch(void* const* d_in, const int* in_sizes, int n_in,
                              void* d_out, int out_size) {
    const float* x      = (const float*)d_in[0];   // [4,256,64,64]
    const float* querys = (const float*)d_in[1];   // [16,256,64,64]
    const float* mu0    = (const float*)d_in[2];   // [1,256,128]
    const float* conv_w = (const float*)d_in[3];   // [256,512,3,3]
    const float* conv_b = (const float*)d_in[4];   // [256]
    float* out    = (float*)d_out;
    float* out_mu = out + (size_t)NIMG * OCH * HWC;

    (void)in_sizes; (void)n_in; (void)out_size;

    cudaFuncSetAttribute(k_conv, cudaFuncAttributeMaxDynamicSharedMemorySize, CONV_SMEM);

    k_init_mu<<<(BB * CC * KD + 255) / 256, 256>>>(mu0);
    k_wq<<<CC, 256>>>(conv_w);   // one-time weight transpose (query half)

    // EM iterations: fused gemm+softmax+colsum, then mu update + l2norm(+zero)
    for (int it = 0; it < STAGE_NUM; ++it) {
        k_gemm_z_em<<<dim3(HWC / 128, BB), 256>>>(x);
        k_gemm_mu<<<dim3(CC / 64, 16, BB), 256>>>(x);
        k_l2norm<<<64, 256>>>();
    }

    // attention: q_z (softmax fused, written transposed [k][hw])
    k_gemm_z_att<<<dim3(HWC / 128, NIMG), 256>>>(querys);

    // fold mu into the rec-half of the conv weights ([b][k][tap][oc])
    k_fold_w<<<dim3(OCH, BB), 128>>>(conv_w);

    // conv over 384 effective channels (querys ++ folded q_z^T) + bias
    k_conv<<<dim3(16, 2, NIMG), 512, CONV_SMEM>>>(querys, conv_b, out);

    // second output: mu
    k_copy_mu<<<(BB * CC * KD + 255) / 256, 256>>>(out_mu);
}

// round 17
// speedup vs baseline: 1.5273x; 1.1304x over previous
#include <cuda_runtime.h>

// Problem constants (fixed shapes from setup_inputs)
#define BB        4
#define NIMG      16      // b*n
#define CC        256
#define HWC       4096    // 64*64
#define KD        128
#define OCH       256
#define IC2       512
#define ICEFF     384     // 256 query channels + 128 folded k-channels
#define EPSF      1e-6f
#define STAGE_NUM 5

typedef unsigned long long ull;

// ---------------------------------------------------------------------------
// f32x2 packed-FMA helpers (sm_100+): 2 fp32 FMAs per instruction, bit-exact.
// ---------------------------------------------------------------------------
__device__ __forceinline__ ull f32x2_pack(float x, float y) {
    ull r;
    asm("mov.b64 %0, {%1, %2};" : "=l"(r)
        : "r"(__float_as_uint(x)), "r"(__float_as_uint(y)));
    return r;
}
__device__ __forceinline__ void f32x2_fma(ull& d, ull a, ull b) {
    asm("fma.rn.f32x2 %0, %1, %2, %0;" : "+l"(d) : "l"(a), "l"(b));
}
__device__ __forceinline__ void f32x2_unpack(ull v, float& x, float& y) {
    unsigned lo, hi;
    asm("mov.b64 {%0, %1}, %2;" : "=r"(lo), "=r"(hi) : "l"(v));
    x = __uint_as_float(lo);
    y = __uint_as_float(hi);
}
__device__ __forceinline__ void cpa16(unsigned dst, const float* src) {
    asm volatile("cp.async.cg.shared.global [%0], [%1], 16;" :: "r"(dst), "l"(src));
}

// ---------------------------------------------------------------------------
// Device scratch (no cudaMalloc allowed)
// ---------------------------------------------------------------------------
__device__ float g_mu[BB * CC * KD];              // current mu   [b][c][k]
__device__ float g_mu_acc[BB * CC * KD];          // accumulation [b][c][k]
__device__ float g_colsum[BB * KD];               // softmax col sums [b][k]
__device__ float g_z[(size_t)BB * HWC * KD];      // EM z  [b][l][k]   (8 MB)
__device__ float g_qzt[(size_t)NIMG * KD * HWC];  // q_z^T [img][k][hw] (32 MB)
__device__ float g_wq[(size_t)CC * 9 * OCH];      // conv_w query half  [ic][tap][oc]
__device__ float g_wf2[(size_t)BB * KD * 9 * OCH];// folded weights [b][k][tap][oc]

// ---------------------------------------------------------------------------
// init mu (broadcast mu0) + zero accumulators
// ---------------------------------------------------------------------------
__global__ void k_init_mu(const float* __restrict__ mu0) {
    int i = blockIdx.x * blockDim.x + threadIdx.x;
    if (i < BB * CC * KD) { g_mu[i] = mu0[i % (CC * KD)]; g_mu_acc[i] = 0.f; }
    if (i < BB * KD)      g_colsum[i] = 0.f;
}

// transpose query-half conv weights once: g_wq[ic][tap][oc] = w[oc][ic][tap]
__global__ void __launch_bounds__(256) k_wq(const float* __restrict__ w) {
    int ic = blockIdx.x;
    int oc = threadIdx.x;
#pragma unroll
    for (int t = 0; t < 9; ++t)
        g_wq[((size_t)ic * 9 + t) * OCH + oc] = w[((size_t)oc * IC2 + ic) * 9 + t];
}

// ---------------------------------------------------------------------------
// EM phase: z[b][l][k] = softmax_k( sum_c x[b][c][l] * mu[b][c][k] )
// Fused softmax + colsum accumulation. Tile 64(l) x 128(k) x 16(c).
// Thread columns k = j*32 + tx*2 + {0,1}. grid (64, B) = 256 blocks.
// ---------------------------------------------------------------------------
__global__ void __launch_bounds__(256) k_gemm_z_em(const float* __restrict__ x) {
    int b  = blockIdx.y;
    int l0 = blockIdx.x * 64;
    const float* A  = x + (size_t)b * CC * HWC;            // [c][l]
    const float* Bm = g_mu + (size_t)b * CC * KD;          // [c][k]
    float*       Cz = g_z + (size_t)b * HWC * KD;          // [l][k]

    __shared__ __align__(16) float As[16][64];
    __shared__ __align__(16) float Bs[16][128];

    int tid = threadIdx.x;
    int tx = tid & 15, ty = tid >> 4;
    ull acc2[4][4];
#pragma unroll
    for (int i = 0; i < 4; ++i)
#pragma unroll
        for (int j = 0; j < 4; ++j) acc2[i][j] = 0ull;

    for (int c0 = 0; c0 < CC; c0 += 16) {
        {   // As: 16c x 64l = 256 float4, one per thread
            int cc = tid >> 4, p4 = (tid & 15) << 2;
            *(float4*)&As[cc][p4] = *(const float4*)&A[(size_t)(c0 + cc) * HWC + l0 + p4];
        }
#pragma unroll
        for (int i = 0; i < 2; ++i) {   // Bs: 16c x 128k = 512 float4
            int lin = tid + i * 256;
            int cc  = lin >> 5;
            int p4  = (lin & 31) << 2;
            *(float4*)&Bs[cc][p4] = *(const float4*)&Bm[(size_t)(c0 + cc) * KD + p4];
        }
        __syncthreads();
#pragma unroll
        for (int cc = 0; cc < 16; ++cc) {
            float a[4];
            *(float4*)&a[0] = *(float4*)&As[cc][ty * 4];
            ull a2[4];
#pragma unroll
            for (int i = 0; i < 4; ++i) a2[i] = f32x2_pack(a[i], a[i]);
            ull b2[4];
#pragma unroll
            for (int j = 0; j < 4; ++j) b2[j] = *(const ull*)&Bs[cc][j * 32 + tx * 2];
#pragma unroll
            for (int i = 0; i < 4; ++i)
#pragma unroll
                for (int j = 0; j < 4; ++j) f32x2_fma(acc2[i][j], a2[i], b2[j]);
        }
        __syncthreads();
    }

    // unpack: column m=2j+s  <->  k = j*32 + tx*2 + s
    float acc[4][8];
#pragma unroll
    for (int i = 0; i < 4; ++i)
#pragma unroll
        for (int j = 0; j < 4; ++j)
            f32x2_unpack(acc2[i][j], acc[i][2 * j], acc[i][2 * j + 1]);

    float p[8];
#pragma unroll
    for (int m = 0; m < 8; ++m) p[m] = 0.f;

#pragma unroll
    for (int i = 0; i < 4; ++i) {
        float mx = acc[i][0];
#pragma unroll
        for (int m = 1; m < 8; ++m) mx = fmaxf(mx, acc[i][m]);
#pragma unroll
        for (int o = 8; o; o >>= 1) mx = fmaxf(mx, __shfl_xor_sync(0xffffffffu, mx, o));
        float s = 0.f;
#pragma unroll
        for (int m = 0; m < 8; ++m) { acc[i][m] = __expf(acc[i][m] - mx); s += acc[i][m]; }
#pragma unroll
        for (int o = 8; o; o >>= 1) s += __shfl_xor_sync(0xffffffffu, s, o);
        float inv = 1.f / s;
#pragma unroll
        for (int m = 0; m < 8; ++m) { acc[i][m] *= inv; p[m] += acc[i][m]; }
        float* dst = &Cz[(size_t)(l0 + ty * 4 + i) * KD + tx * 2];
#pragma unroll
        for (int j = 0; j < 4; ++j)
            *(float2*)(dst + j * 32) = make_float2(acc[i][2 * j], acc[i][2 * j + 1]);
    }

    // reduce colsum partials across the 16 ty-groups (reuse Bs as [16][128])
    float (*cs)[128] = Bs;
#pragma unroll
    for (int j = 0; j < 4; ++j) {
        cs[ty][j * 32 + tx * 2]     = p[2 * j];
        cs[ty][j * 32 + tx * 2 + 1] = p[2 * j + 1];
    }
    __syncthreads();
    if (tid < 128) {
        float t = 0.f;
#pragma unroll
        for (int w2 = 0; w2 < 16; ++w2) t += cs[w2][tid];
        atomicAdd(&g_colsum[b * KD + tid], t);
    }
}

// ---------------------------------------------------------------------------
// Attention phase: q_z = softmax_k(q . mu), written TRANSPOSED: g_qzt[img][k][hw]
// Tile 128(l) x 128(k). grid (32, NIMG) = 512 blocks.
// ---------------------------------------------------------------------------
__global__ void __launch_bounds__(256) k_gemm_z_att(const float* __restrict__ q) {
    int img = blockIdx.y;
    int l0  = blockIdx.x * 128;
    const float* A  = q + (size_t)img * CC * HWC;
    const float* Bm = g_mu + (size_t)(img >> 2) * CC * KD;
    float*       T  = g_qzt + (size_t)img * KD * HWC;      // [k][hw]

    __shared__ __align__(16) float As[16][128];
    __shared__ __align__(16) float Bs[16][128];

    int tid = threadIdx.x;
    int tx = tid & 15, ty = tid >> 4;
    ull acc2[8][4];
#pragma unroll
    for (int i = 0; i < 8; ++i)
#pragma unroll
        for (int j = 0; j < 4; ++j) acc2[i][j] = 0ull;

    for (int c0 = 0; c0 < CC; c0 += 16) {
#pragma unroll
        for (int i = 0; i < 2; ++i) {
            int lin = tid + i * 256;
            int cc  = lin >> 5;
            int p4  = (lin & 31) << 2;
            *(float4*)&As[cc][p4] = *(const float4*)&A[(size_t)(c0 + cc) * HWC + l0 + p4];
            *(float4*)&Bs[cc][p4] = *(const float4*)&Bm[(size_t)(c0 + cc) * KD + p4];
        }
        __syncthreads();
#pragma unroll
        for (int cc = 0; cc < 16; ++cc) {
            float a[8];
            *(float4*)&a[0] = *(float4*)&As[cc][ty * 8];
            *(float4*)&a[4] = *(float4*)&As[cc][ty * 8 + 4];
            ull a2[8];
#pragma unroll
            for (int i = 0; i < 8; ++i) a2[i] = f32x2_pack(a[i], a[i]);
            ull b2[4];
#pragma unroll
            for (int j = 0; j < 4; ++j) b2[j] = *(const ull*)&Bs[cc][j * 32 + tx * 2];
#pragma unroll
            for (int i = 0; i < 8; ++i)
#pragma unroll
                for (int j = 0; j < 4; ++j) f32x2_fma(acc2[i][j], a2[i], b2[j]);
        }
        __syncthreads();
    }

    float acc[8][8];
#pragma unroll
    for (int i = 0; i < 8; ++i)
#pragma unroll
        for (int j = 0; j < 4; ++j)
            f32x2_unpack(acc2[i][j], acc[i][2 * j], acc[i][2 * j + 1]);

#pragma unroll
    for (int i = 0; i < 8; ++i) {
        float mx = acc[i][0];
#pragma unroll
        for (int m = 1; m < 8; ++m) mx = fmaxf(mx, acc[i][m]);
#pragma unroll
        for (int o = 8; o; o >>= 1) mx = fmaxf(mx, __shfl_xor_sync(0xffffffffu, mx, o));
        float s = 0.f;
#pragma unroll
        for (int m = 0; m < 8; ++m) { acc[i][m] = __expf(acc[i][m] - mx); s += acc[i][m]; }
#pragma unroll
        for (int o = 8; o; o >>= 1) s += __shfl_xor_sync(0xffffffffu, s, o);
        float inv = 1.f / s;
#pragma unroll
        for (int m = 0; m < 8; ++m) acc[i][m] *= inv;
    }

    // transposed store: row k = j*32 + tx*2 + s, 8 consecutive hw positions
#pragma unroll
    for (int m = 0; m < 8; ++m) {
        int k = (m >> 1) * 32 + tx * 2 + (m & 1);
        float* dst = &T[(size_t)k * HWC + l0 + ty * 8];
        *(float4*)dst       = make_float4(acc[0][m], acc[1][m], acc[2][m], acc[3][m]);
        *(float4*)(dst + 4) = make_float4(acc[4][m], acc[5][m], acc[6][m], acc[7][m]);
    }
}

// ---------------------------------------------------------------------------
// mu_acc[b][c][k] += sum_{l in chunk} x[b][c][l] * z[b][l][k]
// (1/(EPS+colsum) scaling moved to k_l2norm — per-k scalar, constant over c.)
// Split over l (32 chunks of 128). BM=64(c), BN=128(k), BK=32(l).
// grid: (4, 32, B) = 512 blocks, 256 threads, 4x8 per thread.
// ---------------------------------------------------------------------------
__global__ void __launch_bounds__(256) k_gemm_mu(const float* __restrict__ x) {
    int b  = blockIdx.z;
    int c0 = blockIdx.x * 64;
    int l0 = blockIdx.y * 128;
    const float* A    = x + (size_t)b * CC * HWC;          // [c][l]
    const float* Bsrc = g_z + (size_t)b * HWC * KD;        // [l][k]

    __shared__ __align__(16) float As[32][68];   // [l][c] transposed (+pad)
    __shared__ __align__(16) float Bs[32][128];  // [l][k]

    int tid = threadIdx.x;
    int tx = tid & 15, ty = tid >> 4;
    ull acc2[4][4];
#pragma unroll
    for (int i = 0; i < 4; ++i)
#pragma unroll
        for (int j = 0; j < 4; ++j) acc2[i][j] = 0ull;

    for (int lb = 0; lb < 128; lb += 32) {
#pragma unroll
        for (int i = 0; i < 2; ++i) {                  // A: 64c x 32l -> [l][c]
            int lin = tid + i * 256;                   // float4 units, 512
            int cc  = lin >> 3;
            int l4  = (lin & 7) << 2;
            float4 va = *(const float4*)&A[(size_t)(c0 + cc) * HWC + l0 + lb + l4];
            As[l4 + 0][cc] = va.x; As[l4 + 1][cc] = va.y;
            As[l4 + 2][cc] = va.z; As[l4 + 3][cc] = va.w;
        }
#pragma unroll
        for (int i = 0; i < 4; ++i) {                  // B: 32l x 128k
            int lin = tid + i * 256;                   // float4 units, 1024
            int ll  = lin >> 5;
            int k4  = (lin & 31) << 2;
            *(float4*)&Bs[ll][k4] = *(const float4*)&Bsrc[(size_t)(l0 + lb + ll) * KD + k4];
        }
        __syncthreads();
#pragma unroll
        for (int ll = 0; ll < 32; ++ll) {
            float a[4];
            *(float4*)&a[0] = *(float4*)&As[ll][ty * 4];
            ull a2[4];
#pragma unroll
            for (int i = 0; i < 4; ++i) a2[i] = f32x2_pack(a[i], a[i]);
            ull b2[4];
#pragma unroll
            for (int j = 0; j < 4; ++j) b2[j] = *(const ull*)&Bs[ll][j * 32 + tx * 2];
#pragma unroll
            for (int i = 0; i < 4; ++i)
#pragma unroll
                for (int j = 0; j < 4; ++j) f32x2_fma(acc2[i][j], a2[i], b2[j]);
        }
        __syncthreads();
    }
#pragma unroll
    for (int i = 0; i < 4; ++i)
#pragma unroll
        for (int j = 0; j < 4; ++j) {
            float v0, v1;
            f32x2_unpack(acc2[i][j], v0, v1);
            size_t base = (size_t)b * CC * KD + (size_t)(c0 + ty * 4 + i) * KD + j * 32 + tx * 2;
            atomicAdd(&g_mu_acc[base],     v0);
            atomicAdd(&g_mu_acc[base + 1], v1);
        }
}

// ---------------------------------------------------------------------------
// mu[b][c][k] = l2norm_c( mu_acc[b][:][k] / (EPS + colsum[b][k]) )
// Also zeroes mu_acc and colsum for the next iteration.
// ---------------------------------------------------------------------------
__global__ void __launch_bounds__(256) k_l2norm() {
    int gw = blockIdx.x * 8 + (threadIdx.x >> 5);   // 0..511
    int lane = threadIdx.x & 31;
    int b = gw >> 7;
    int k = gw & 127;
    float ics = 1.f / (EPSF + g_colsum[b * KD + k]);
    float v[8];
    float ss = 0.f;
#pragma unroll
    for (int i = 0; i < 8; ++i) {
        size_t idx = (size_t)(b * CC + lane + i * 32) * KD + k;
        v[i] = g_mu_acc[idx] * ics;
        g_mu_acc[idx] = 0.f;
        ss += v[i] * v[i];
    }
#pragma unroll
    for (int o = 16; o; o >>= 1) ss += __shfl_xor_sync(0xffffffffu, ss, o);
    float inv = 1.f / (EPSF + sqrtf(ss));
#pragma unroll
    for (int i = 0; i < 8; ++i)
        g_mu[(size_t)(b * CC + lane + i * 32) * KD + k] = v[i] * inv;
    if (lane == 0) g_colsum[b * KD + k] = 0.f;
}

// ---------------------------------------------------------------------------
// Fold mu into the rec-half of the conv weights, output layout [b][k][tap][oc]:
//   wf2[b][k][tap][oc] = sum_c w[oc][256+c][tap] * mu[b][c][k]
// grid (OCH, BB), 128 threads (one per k).
// ---------------------------------------------------------------------------
__global__ void __launch_bounds__(128) k_fold_w(const float* __restrict__ w) {
    int oc = blockIdx.x;
    int b  = blockIdx.y;
    int k  = threadIdx.x;
    float acc[9];
#pragma unroll
    for (int t = 0; t < 9; ++t) acc[t] = 0.f;
    const float* wbase = w + ((size_t)oc * IC2 + CC) * 9;
    const float* mubase = g_mu + (size_t)b * CC * KD + k;
    for (int c = 0; c < CC; ++c) {
        float m = mubase[(size_t)c * KD];
        const float* wr = wbase + (size_t)c * 9;
#pragma unroll
        for (int t = 0; t < 9; ++t) acc[t] = fmaf(m, __ldg(&wr[t]), acc[t]);
    }
#pragma unroll
    for (int t = 0; t < 9; ++t)
        g_wf2[(((size_t)b * KD + k) * 9 + t) * OCH + oc] = acc[t];
}

// ---------------------------------------------------------------------------
// 3x3 SAME conv over 384 effective input channels, double-buffered cp.async:
//   ic <  256: querys channel ic, weights from g_wq  [ic][tap][oc]
//   ic >= 256: q_z^T channel (ic-256), weights from g_wf2[b] [k][tap][oc]
// Block: 1 img, 4 rows x 64 cols (256 pos), 64 oc. 256 threads, 2 blocks/SM.
// Thread: 8 cols x 8 oc (oc = ocb + j*16 + tx*2 + s) with f32x2 FMAs.
// in row stride = 72 floats: [0..3] left pad, [4..67] data, [68..71] right pad
// (fixes the R16 OOB read at offset 68). grid (16, 4, 16) = 1024 blocks.
// ---------------------------------------------------------------------------
#define CBKC      4
#define NCHUNK    (ICEFF / CBKC)           // 96
#define INROW     72
#define INS_FLT   (2 * CBKC * 6 * INROW)   // 3456
#define WS_FLT    (2 * 36 * 64)            // 4608

__global__ void __launch_bounds__(256, 2) k_conv(const float* __restrict__ q,
                                                 const float* __restrict__ bias,
                                                 float* __restrict__ out) {
    __shared__ __align__(16) float insf[INS_FLT];   // [2][4][6][72]
    __shared__ __align__(16) float wsf[WS_FLT];     // [2][36][64]
    unsigned sb_in, sb_w;
    asm("{ .reg .u64 t; cvta.to.shared.u64 t, %1; cvt.u32.u64 %0, t; }"
        : "=r"(sb_in) : "l"((float*)insf));
    asm("{ .reg .u64 t; cvta.to.shared.u64 t, %1; cvt.u32.u64 %0, t; }"
        : "=r"(sb_w) : "l"((float*)wsf));

    int img = blockIdx.z;
    int b   = img >> 2;
    int ocb = blockIdx.y * 64;
    int r0  = blockIdx.x * 4;

    int tid  = threadIdx.x;
    int tx   = tid & 7;            // oc = ocb + j*16 + tx*2 + s
    int tp   = tid >> 3;           // 0..31
    int prow = tp >> 3;            // 0..3
    int pcol = (tp & 7) * 8;       // 0..56

    const float* qimg   = q + (size_t)img * CC * HWC;
    const float* zimg   = g_qzt + (size_t)img * KD * HWC;
    const float* wfoldb = g_wf2 + (size_t)b * KD * 9 * OCH;

    // zero input staging (pads / OOB rows stay zero forever)
    for (int i = tid; i < INS_FLT; i += 256) insf[i] = 0.f;
    __syncthreads();

    // chunk issue: 384 input + 576 weight cp.asyncs (16B each)
    auto issue = [&](int buf, int chunk) {
        int icb = chunk * CBKC;
        const float* srcp = (icb < CC) ? qimg + (size_t)icb * HWC
                                       : zimg + (size_t)(icb - CC) * HWC;
        const float* wsrc = (icb < CC) ? g_wq + (size_t)icb * 9 * OCH
                                       : wfoldb + (size_t)(icb - CC) * 9 * OCH;
#pragma unroll
        for (int kk = 0; kk < 4; ++kk) {
            int op = tid + kk * 256;           // 0..1023
            if (op < 384) {
                int ic  = op / 96;
                int rr  = (op / 16) % 6;
                int seg = op & 15;
                int y   = r0 - 1 + rr;
                if ((unsigned)y < 64u)
                    cpa16(sb_in + (((buf * CBKC + ic) * 6 + rr) * INROW + 4 + seg * 4) * 4,
                          srcp + (size_t)ic * HWC + y * 64 + seg * 4);
            } else if (op < 960) {
                int wop = op - 384;            // 0..575
                int row = wop >> 4;            // ic*9+tap, 0..35
                int seg = wop & 15;
                cpa16(sb_w + ((buf * 36 + row) * 64 + seg * 4) * 4,
                      wsrc + (size_t)row * OCH + ocb + seg * 4);
            }
        }
        asm volatile("cp.async.commit_group;" ::: "memory");
    };

    ull acc2[8][4];
#pragma unroll
    for (int i = 0; i < 8; ++i)
#pragma unroll
        for (int j = 0; j < 4; ++j) acc2[i][j] = 0ull;

    issue(0, 0);
    asm volatile("cp.async.wait_group 0;" ::: "memory");
    __syncthreads();

    int buf = 0;
    for (int chunk = 0; chunk < NCHUNK; ++chunk) {
        if (chunk + 1 < NCHUNK) issue(buf ^ 1, chunk + 1);
        // compute on buf
#pragma unroll
        for (int ic = 0; ic < CBKC; ++ic) {
            int ib = (buf * CBKC + ic) * 6;
#pragma unroll
            for (int ky = 0; ky < 3; ++ky) {
                const float* rowp = insf + (ib + prow + ky) * INROW + 3 + pcol;
                float a10[10];
#pragma unroll
                for (int t = 0; t < 10; ++t) a10[t] = rowp[t];
                ull a2[10];
#pragma unroll
                for (int t = 0; t < 10; ++t) a2[t] = f32x2_pack(a10[t], a10[t]);
#pragma unroll
                for (int kx = 0; kx < 3; ++kx) {
                    const ull* wp = (const ull*)(wsf + (buf * 36 + ic * 9 + ky * 3 + kx) * 64 + tx * 2);
                    ull b2[4];
#pragma unroll
                    for (int j = 0; j < 4; ++j) b2[j] = wp[j * 8];
#pragma unroll
                    for (int i = 0; i < 8; ++i)
#pragma unroll
                        for (int j = 0; j < 4; ++j)
                            f32x2_fma(acc2[i][j], a2[kx + i], b2[j]);
                }
            }
        }
        if (chunk + 1 < NCHUNK)
            asm volatile("cp.async.wait_group 0;" ::: "memory");
        __syncthreads();
        buf ^= 1;
    }

    // epilogue: unpack + bias; oc = ocb + j*16 + tx*2 + s
#pragma unroll
    for (int j = 0; j < 4; ++j) {
        float v0[8], v1[8];
#pragma unroll
        for (int i = 0; i < 8; ++i) f32x2_unpack(acc2[i][j], v0[i], v1[i]);
#pragma unroll
        for (int s = 0; s < 2; ++s) {
            int oc = ocb + j * 16 + tx * 2 + s;
            float bv = bias[oc];
            const float* v = s ? v1 : v0;
            float* dst = out + ((size_t)img * OCH + oc) * HWC + (r0 + prow) * 64 + pcol;
            *(float4*)dst       = make_float4(v[0] + bv, v[1] + bv, v[2] + bv, v[3] + bv);
            *(float4*)(dst + 4) = make_float4(v[4] + bv, v[5] + bv, v[6] + bv, v[7] + bv);
        }
    }
}

__global__ void k_copy_mu(float* __restrict__ out_mu) {
    int i = blockIdx.x * blockDim.x + threadIdx.x;
    if (i < BB * CC * KD) out_mu[i] = g_mu[i];
}

// ---------------------------------------------------------------------------
// launch
// ---------------------------------------------------------------------------
extern "C" void kernel_launch(void* const* d_in, const int* in_sizes, int n_in,
                              void* d_out, int out_size) {
    const float* x      = (const float*)d_in[0];   // [4,256,64,64]
    const float* querys = (const float*)d_in[1];   // [16,256,64,64]
    const float* mu0    = (const float*)d_in[2];   // [1,256,128]
    const float* conv_w = (const float*)d_in[3];   // [256,512,3,3]
    const float* conv_b = (const float*)d_in[4];   // [256]
    float* out    = (float*)d_out;
    float* out_mu = out + (size_t)NIMG * OCH * HWC;

    (void)in_sizes; (void)n_in; (void)out_size;

    k_init_mu<<<(BB * CC * KD + 255) / 256, 256>>>(mu0);
    k_wq<<<CC, 256>>>(conv_w);   // one-time weight transpose (query half)

    // EM iterations: fused gemm+softmax+colsum, then mu update + l2norm(+zero)
    for (int it = 0; it < STAGE_NUM; ++it) {
        k_gemm_z_em<<<dim3(HWC / 64, BB), 256>>>(x);
        k_gemm_mu<<<dim3(CC / 64, 32, BB), 256>>>(x);
        k_l2norm<<<64, 256>>>();
    }

    // attention: q_z (softmax fused, written transposed [k][hw])
    k_gemm_z_att<<<dim3(HWC / 128, NIMG), 256>>>(querys);

    // fold mu into the rec-half of the conv weights ([b][k][tap][oc])
    k_fold_w<<<dim3(OCH, BB), 128>>>(conv_w);

    // conv over 384 effective channels (querys ++ folded q_z^T) + bias
    k_conv<<<dim3(16, 4, NIMG), 256>>>(querys, conv_b, out);

    // second output: mu
    k_copy_mu<<<(BB * CC * KD + 255) / 256, 256>>>(out_mu);
}